// round 7
// baseline (speedup 1.0000x reference)
#include <cuda_runtime.h>
#include <math.h>
#include <stdint.h>

#define NWL 262144
#define NL 10

// Globals carrying prep-kernel results to the main kernel.
__device__ float g_nu0[NL], g_isig[NL], g_y[NL], g_amp[NL];
__device__ float g_h[32];
__device__ float g_m[64];

__device__ __forceinline__ float sigmoidf_(float z) { return 1.0f / (1.0f + expf(-z)); }
__device__ __forceinline__ float siluf_(float z)    { return z / (1.0f + expf(-z)); }
__device__ __forceinline__ float softplusf_(float z){ return log1pf(expf(-fabsf(z))) + fmaxf(z, 0.0f); }

// L2-persistent (evict_last) read-only vector load via cache-hint policy.
__device__ __forceinline__ uint64_t make_policy_el() {
    uint64_t pol;
    asm("createpolicy.fractional.L2::evict_last.b64 %0, 1.0;" : "=l"(pol));
    return pol;
}
__device__ __forceinline__ float4 ldg_el4(const float4* p, uint64_t pol) {
    float4 v;
    asm volatile("ld.global.nc.L2::cache_hint.v4.f32 {%0,%1,%2,%3}, [%4], %5;"
                 : "=f"(v.x), "=f"(v.y), "=f"(v.z), "=f"(v.w) : "l"(p), "l"(pol));
    return v;
}

// Unnormalized Voigt w(x,y) mirroring the reference's branch structure.
__device__ __forceinline__ float voigt_w(float x, float y) {
    float ax = fabsf(x);
    float s  = ax + y;
    float tr = y, ti = -x;
    float ur = y * y - x * x;
    float ui = -2.0f * x * y;
    if (s >= 15.0f) {
        float dr = 0.5f + ur, di = ui;
        float nr = 0.5641896f * tr, ni = 0.5641896f * ti;
        return (nr * dr + ni * di) / (dr * dr + di * di);
    } else if (ax >= 5.5f) {
        float cr = 1.410474f + 0.5641896f * ur;
        float ci = 0.5641896f * ui;
        float nr = tr * cr - ti * ci, ni = tr * ci + ti * cr;
        float u2r = ur * ur - ui * ui, u2i = 2.0f * ur * ui;
        float dr = 0.75f + 3.0f * ur + u2r;
        float di = 3.0f * ui + u2i;
        return (nr * dr + ni * di) / (dr * dr + di * di);
    } else {
        float x2 = x * x;
        return expf(-x2) * cosf(2.0f * x * y) * 0.5641895835f
             + 0.6366197724f * y * sinf(x2) / (x2 + y * y + 1e-10f);
    }
}

__device__ __forceinline__ float line_sum(float wl, const float* nu0, const float* isg,
                                          const float* yy, const float* amp) {
    float sum = 0.0f;
#pragma unroll
    for (int l = 0; l < NL; l++) {
        float x = (wl - nu0[l]) * isg[l];
        sum += amp[l] * voigt_w(x, yy[l]);
    }
    return sum;
}

// ---------------------------------------------------------------------------
// Prep kernel (one block): line params, continuum hidden h, cross[:8], mixing m.
// ---------------------------------------------------------------------------
__global__ void prep_kernel(const float* __restrict__ wl,
                            const float* __restrict__ pT, const float* __restrict__ pP,
                            const float* __restrict__ po3, const float* __restrict__ ph2o,
                            const float* __restrict__ pco2,
                            const float* __restrict__ mw1, const float* __restrict__ mb1,
                            const float* __restrict__ mw2, const float* __restrict__ mb2,
                            const float* __restrict__ cw1, const float* __restrict__ cb1,
                            const float* __restrict__ cw2, const float* __restrict__ cb2) {
    __shared__ float sh_h[32], sh_c8[8], sh_m1[64];
    __shared__ float s_nu0[NL], s_is[NL], s_y[NL], s_amp[NL];

    const float LN_nu0[NL]  = {254.0f, 280.0f, 310.0f, 940.0f, 1130.0f, 1380.0f, 1400.0f, 1600.0f, 2000.0f, 2700.0f};
    const float LN_str[NL]  = {1.15e-17f, 5e-18f, 1.9e-19f, 2.5e-23f, 8.2e-24f, 1.8e-22f, 3.5e-25f, 7.8e-26f, 4.2e-24f, 1.2e-24f};
    const float LN_w[NL]    = {2.0f, 3.0f, 2.5f, 3.0f, 2.5f, 4.0f, 3.0f, 2.5f, 4.0f, 3.5f};
    const float LN_te[NL]   = {0.05f, 0.04f, 0.03f, 0.4f, 0.35f, 0.45f, 0.5f, 0.48f, 0.52f, 0.49f};
    const float LN_mass[NL] = {48.0f, 48.0f, 48.0f, 18.0f, 18.0f, 18.0f, 44.0f, 44.0f, 44.0f, 44.0f};

    int t = threadIdx.x;
    float T = pT[0];
    float P = pP[0];

    if (t < NL) {
        float conc = (t < 3) ? po3[0] : ((t < 6) ? ph2o[0] : pco2[0]);
        float sT  = LN_str[t] * powf(273.15f / (T + 1e-12f), LN_te[t]);
        float gL  = LN_w[t] * (P / (101325.0f + 1e-12f)) * sqrtf(273.15f / (T + 1e-12f));
        float gD  = LN_nu0[t] / 299792458.0f *
                    sqrtf(2.0f * 1.380649e-23f * T * 6.02214076e23f / (LN_mass[t] + 1e-12f));
        float sig = gD / (1.1774100226f + 1e-12f);
        float isg = 1.0f / (sig + 1e-12f);
        float y   = gL * isg;
        float amp = conc * sT / (sig * 1.7724538509f + 1e-12f);
        s_nu0[t] = LN_nu0[t]; s_is[t] = isg; s_y[t] = y; s_amp[t] = amp;
        g_nu0[t] = LN_nu0[t]; g_isig[t] = isg; g_y[t] = y; g_amp[t] = amp;
    }
    if (t < 32) {
        float feat[5] = {T / (273.15f + 1e-12f), P / (101325.0f + 1e-12f), ph2o[0], 1.0f, 0.0f};
        float a = cb1[t];
#pragma unroll
        for (int i = 0; i < 5; i++) a += feat[i] * cw1[i * 32 + t];
        float hv = siluf_(a);
        sh_h[t] = hv;
        g_h[t]  = hv;
    }
    __syncthreads();

    if (t < 8) {
        float a = cb2[t];
#pragma unroll
        for (int k = 0; k < 32; k++) a += sh_h[k] * cw2[k * NWL + t];
        sh_c8[t] = line_sum(wl[t], s_nu0, s_is, s_y, s_amp) + softplusf_(a);
    }
    __syncthreads();

    if (t < 64) {
        float f0 = T / (273.15f + 1e-12f);
        float f1 = P / (101325.0f + 1e-12f);
        float a = mb1[t] + f0 * mw1[0 * 64 + t] + f1 * mw1[1 * 64 + t];
#pragma unroll
        for (int i = 0; i < 8; i++) a += sh_c8[i] * mw1[(2 + i) * 64 + t];
        sh_m1[t] = siluf_(a);
    }
    __syncthreads();

    if (t < 64) {
        float a = mb2[t];
#pragma unroll
        for (int k = 0; k < 64; k++) a += sh_m1[k] * mw2[k * 64 + t];
        g_m[t] = siluf_(a);
    }
}

// ---------------------------------------------------------------------------
// Main kernel: 4 wl/thread (float4), evict_last weight loads (keep the 97MB
// stream L2-resident across graph replays), 2-deep register prefetch.
// ---------------------------------------------------------------------------
__global__ void __launch_bounds__(128) main_kernel(const float4* __restrict__ wl4,
                                                   const float4* __restrict__ cw2,
                                                   const float4* __restrict__ cb2,
                                                   const float4* __restrict__ mw3,
                                                   const float4* __restrict__ mb3,
                                                   float4* __restrict__ out) {
    __shared__ float sh_h[32], sh_m[64];
    __shared__ float s_nu0[NL], s_is[NL], s_y[NL], s_amp[NL];
    int t = threadIdx.x;
    if (t < 32) sh_h[t] = g_h[t];
    else if (t < 96) sh_m[t - 32] = g_m[t - 32];
    else if (t < 96 + NL) {
        int l = t - 96;
        s_nu0[l] = g_nu0[l]; s_is[l] = g_isig[l]; s_y[l] = g_y[l]; s_amp[l] = g_amp[l];
    }
    __syncthreads();

    const int stride4 = NWL / 4;
    int i = blockIdx.x * blockDim.x + t;

    uint64_t pol = make_policy_el();

    float4 wl = ldg_el4(&wl4[i], pol);

    // Per-block row-order rotation.
    int rotC = (blockIdx.x * 7)  & 31;
    int rotM = (blockIdx.x * 11) & 63;

    float4 buf[2][4];

    // ---- Continuum dot: 32 rows, 8 chunks of 4, prefetch depth 2 ----
    float4 c = ldg_el4(&cb2[i], pol);
#pragma unroll
    for (int j = 0; j < 4; j++) {
        int kk = (j + rotC) & 31;
        buf[0][j] = ldg_el4(&cw2[kk * stride4 + i], pol);
    }
#pragma unroll
    for (int ch = 0; ch < 8; ch++) {
        int cur = ch & 1;
        if (ch < 7) {
#pragma unroll
            for (int j = 0; j < 4; j++) {
                int kk = ((ch + 1) * 4 + j + rotC) & 31;
                buf[cur ^ 1][j] = ldg_el4(&cw2[kk * stride4 + i], pol);
            }
        }
#pragma unroll
        for (int j = 0; j < 4; j++) {
            int kk = (ch * 4 + j + rotC) & 31;
            float hk = sh_h[kk];
            float4 w = buf[cur][j];
            c.x = fmaf(hk, w.x, c.x);
            c.y = fmaf(hk, w.y, c.y);
            c.z = fmaf(hk, w.z, c.z);
            c.w = fmaf(hk, w.w, c.w);
        }
    }

    // ---- Mixing dot: 64 rows, 16 chunks of 4, prefetch depth 2 ----
    float4 d = ldg_el4(&mb3[i], pol);
#pragma unroll
    for (int j = 0; j < 4; j++) {
        int kk = (j + rotM) & 63;
        buf[0][j] = ldg_el4(&mw3[kk * stride4 + i], pol);
    }
#pragma unroll
    for (int ch = 0; ch < 16; ch++) {
        int cur = ch & 1;
        if (ch < 15) {
#pragma unroll
            for (int j = 0; j < 4; j++) {
                int kk = ((ch + 1) * 4 + j + rotM) & 63;
                buf[cur ^ 1][j] = ldg_el4(&mw3[kk * stride4 + i], pol);
            }
        }
#pragma unroll
        for (int j = 0; j < 4; j++) {
            int kk = (ch * 4 + j + rotM) & 63;
            float mk = sh_m[kk];
            float4 w = buf[cur][j];
            d.x = fmaf(mk, w.x, d.x);
            d.y = fmaf(mk, w.y, d.y);
            d.z = fmaf(mk, w.z, d.z);
            d.w = fmaf(mk, w.w, d.w);
        }
    }

    float cr0 = line_sum(wl.x, s_nu0, s_is, s_y, s_amp) + softplusf_(c.x);
    float cr1 = line_sum(wl.y, s_nu0, s_is, s_y, s_amp) + softplusf_(c.y);
    float cr2 = line_sum(wl.z, s_nu0, s_is, s_y, s_amp) + softplusf_(c.z);
    float cr3 = line_sum(wl.w, s_nu0, s_is, s_y, s_amp) + softplusf_(c.w);

    float4 o;
    o.x = cr0 * (1.0f + 0.1f * (sigmoidf_(d.x) - 0.5f));
    o.y = cr1 * (1.0f + 0.1f * (sigmoidf_(d.y) - 0.5f));
    o.z = cr2 * (1.0f + 0.1f * (sigmoidf_(d.z) - 0.5f));
    o.w = cr3 * (1.0f + 0.1f * (sigmoidf_(d.w) - 0.5f));
    out[i] = o;
}

extern "C" void kernel_launch(void* const* d_in, const int* in_sizes, int n_in,
                              void* d_out, int out_size) {
    const float* wl   = (const float*)d_in[0];
    const float* pT   = (const float*)d_in[1];
    const float* pP   = (const float*)d_in[2];
    const float* po3  = (const float*)d_in[3];
    const float* ph2o = (const float*)d_in[4];
    const float* pco2 = (const float*)d_in[5];
    const float* mw1  = (const float*)d_in[6];
    const float* mb1  = (const float*)d_in[7];
    const float* mw2  = (const float*)d_in[8];
    const float* mb2  = (const float*)d_in[9];
    const float* mw3  = (const float*)d_in[10];
    const float* mb3  = (const float*)d_in[11];
    const float* cw1  = (const float*)d_in[12];
    const float* cb1  = (const float*)d_in[13];
    const float* cw2  = (const float*)d_in[14];
    const float* cb2  = (const float*)d_in[15];

    prep_kernel<<<1, 64>>>(wl, pT, pP, po3, ph2o, pco2,
                           mw1, mb1, mw2, mb2, cw1, cb1, cw2, cb2);

    const int vec = NWL / 4;           // 65536 threads, 4 wl each
    main_kernel<<<vec / 128, 128>>>((const float4*)wl,
                                    (const float4*)cw2, (const float4*)cb2,
                                    (const float4*)mw3, (const float4*)mb3,
                                    (float4*)d_out);
}

// round 9
// speedup vs baseline: 1.4836x; 1.4836x over previous
#include <cuda_runtime.h>
#include <math.h>
#include <stdint.h>

#define NWL 262144
#define NL 10

// Globals carrying prep-kernel results to the main kernel.
__device__ float g_nu0[NL], g_isig[NL], g_y[NL], g_amp[NL];
__device__ float g_h[32];
__device__ float g_m[64];

__device__ __forceinline__ float sigmoidf_(float z) { return 1.0f / (1.0f + expf(-z)); }
__device__ __forceinline__ float siluf_(float z)    { return z / (1.0f + expf(-z)); }
__device__ __forceinline__ float softplusf_(float z){ return log1pf(expf(-fabsf(z))) + fmaxf(z, 0.0f); }

// L2 eviction-class policies.
__device__ __forceinline__ uint64_t make_policy_last() {
    uint64_t pol;
    asm("createpolicy.fractional.L2::evict_last.b64 %0, 1.0;" : "=l"(pol));
    return pol;
}
__device__ __forceinline__ uint64_t make_policy_first() {
    uint64_t pol;
    asm("createpolicy.fractional.L2::evict_first.b64 %0, 1.0;" : "=l"(pol));
    return pol;
}
__device__ __forceinline__ float4 ldg_pol4(const float4* p, uint64_t pol) {
    float4 v;
    asm volatile("ld.global.nc.L2::cache_hint.v4.f32 {%0,%1,%2,%3}, [%4], %5;"
                 : "=f"(v.x), "=f"(v.y), "=f"(v.z), "=f"(v.w) : "l"(p), "l"(pol));
    return v;
}

// Unnormalized Voigt w(x,y) mirroring the reference's branch structure.
__device__ __forceinline__ float voigt_w(float x, float y) {
    float ax = fabsf(x);
    float s  = ax + y;
    float tr = y, ti = -x;
    float ur = y * y - x * x;
    float ui = -2.0f * x * y;
    if (s >= 15.0f) {
        float dr = 0.5f + ur, di = ui;
        float nr = 0.5641896f * tr, ni = 0.5641896f * ti;
        return (nr * dr + ni * di) / (dr * dr + di * di);
    } else if (ax >= 5.5f) {
        float cr = 1.410474f + 0.5641896f * ur;
        float ci = 0.5641896f * ui;
        float nr = tr * cr - ti * ci, ni = tr * ci + ti * cr;
        float u2r = ur * ur - ui * ui, u2i = 2.0f * ur * ui;
        float dr = 0.75f + 3.0f * ur + u2r;
        float di = 3.0f * ui + u2i;
        return (nr * dr + ni * di) / (dr * dr + di * di);
    } else {
        float x2 = x * x;
        return expf(-x2) * cosf(2.0f * x * y) * 0.5641895835f
             + 0.6366197724f * y * sinf(x2) / (x2 + y * y + 1e-10f);
    }
}

__device__ __forceinline__ float line_sum(float wl, const float* nu0, const float* isg,
                                          const float* yy, const float* amp) {
    float sum = 0.0f;
#pragma unroll
    for (int l = 0; l < NL; l++) {
        float x = (wl - nu0[l]) * isg[l];
        sum += amp[l] * voigt_w(x, yy[l]);
    }
    return sum;
}

// ---------------------------------------------------------------------------
// Prep kernel (one block): line params, continuum hidden h, cross[:8], mixing m.
// ---------------------------------------------------------------------------
__global__ void prep_kernel(const float* __restrict__ wl,
                            const float* __restrict__ pT, const float* __restrict__ pP,
                            const float* __restrict__ po3, const float* __restrict__ ph2o,
                            const float* __restrict__ pco2,
                            const float* __restrict__ mw1, const float* __restrict__ mb1,
                            const float* __restrict__ mw2, const float* __restrict__ mb2,
                            const float* __restrict__ cw1, const float* __restrict__ cb1,
                            const float* __restrict__ cw2, const float* __restrict__ cb2) {
    __shared__ float sh_h[32], sh_c8[8], sh_m1[64];
    __shared__ float s_nu0[NL], s_is[NL], s_y[NL], s_amp[NL];

    const float LN_nu0[NL]  = {254.0f, 280.0f, 310.0f, 940.0f, 1130.0f, 1380.0f, 1400.0f, 1600.0f, 2000.0f, 2700.0f};
    const float LN_str[NL]  = {1.15e-17f, 5e-18f, 1.9e-19f, 2.5e-23f, 8.2e-24f, 1.8e-22f, 3.5e-25f, 7.8e-26f, 4.2e-24f, 1.2e-24f};
    const float LN_w[NL]    = {2.0f, 3.0f, 2.5f, 3.0f, 2.5f, 4.0f, 3.0f, 2.5f, 4.0f, 3.5f};
    const float LN_te[NL]   = {0.05f, 0.04f, 0.03f, 0.4f, 0.35f, 0.45f, 0.5f, 0.48f, 0.52f, 0.49f};
    const float LN_mass[NL] = {48.0f, 48.0f, 48.0f, 18.0f, 18.0f, 18.0f, 44.0f, 44.0f, 44.0f, 44.0f};

    int t = threadIdx.x;
    float T = pT[0];
    float P = pP[0];

    if (t < NL) {
        float conc = (t < 3) ? po3[0] : ((t < 6) ? ph2o[0] : pco2[0]);
        float sT  = LN_str[t] * powf(273.15f / (T + 1e-12f), LN_te[t]);
        float gL  = LN_w[t] * (P / (101325.0f + 1e-12f)) * sqrtf(273.15f / (T + 1e-12f));
        float gD  = LN_nu0[t] / 299792458.0f *
                    sqrtf(2.0f * 1.380649e-23f * T * 6.02214076e23f / (LN_mass[t] + 1e-12f));
        float sig = gD / (1.1774100226f + 1e-12f);
        float isg = 1.0f / (sig + 1e-12f);
        float y   = gL * isg;
        float amp = conc * sT / (sig * 1.7724538509f + 1e-12f);
        s_nu0[t] = LN_nu0[t]; s_is[t] = isg; s_y[t] = y; s_amp[t] = amp;
        g_nu0[t] = LN_nu0[t]; g_isig[t] = isg; g_y[t] = y; g_amp[t] = amp;
    }
    if (t < 32) {
        float feat[5] = {T / (273.15f + 1e-12f), P / (101325.0f + 1e-12f), ph2o[0], 1.0f, 0.0f};
        float a = cb1[t];
#pragma unroll
        for (int i = 0; i < 5; i++) a += feat[i] * cw1[i * 32 + t];
        float hv = siluf_(a);
        sh_h[t] = hv;
        g_h[t]  = hv;
    }
    __syncthreads();

    if (t < 8) {
        float a = cb2[t];
#pragma unroll
        for (int k = 0; k < 32; k++) a += sh_h[k] * cw2[k * NWL + t];
        sh_c8[t] = line_sum(wl[t], s_nu0, s_is, s_y, s_amp) + softplusf_(a);
    }
    __syncthreads();

    if (t < 64) {
        float f0 = T / (273.15f + 1e-12f);
        float f1 = P / (101325.0f + 1e-12f);
        float a = mb1[t] + f0 * mw1[0 * 64 + t] + f1 * mw1[1 * 64 + t];
#pragma unroll
        for (int i = 0; i < 8; i++) a += sh_c8[i] * mw1[(2 + i) * 64 + t];
        sh_m1[t] = siluf_(a);
    }
    __syncthreads();

    if (t < 64) {
        float a = mb2[t];
#pragma unroll
        for (int k = 0; k < 64; k++) a += sh_m1[k] * mw2[k * 64 + t];
        g_m[t] = siluf_(a);
    }
}

// ---------------------------------------------------------------------------
// Main kernel: 4 wl/thread (float4). L2 eviction-class split: mw3 (64MB,
// 2/3 of traffic) evict_last so it stays L2-resident across graph replays;
// cw2/wl/cb2/mb3 (33MB) evict_first so the streaming part never displaces it.
// ---------------------------------------------------------------------------
__global__ void __launch_bounds__(128) main_kernel(const float4* __restrict__ wl4,
                                                   const float4* __restrict__ cw2,
                                                   const float4* __restrict__ cb2,
                                                   const float4* __restrict__ mw3,
                                                   const float4* __restrict__ mb3,
                                                   float4* __restrict__ out) {
    __shared__ float sh_h[32], sh_m[64];
    __shared__ float s_nu0[NL], s_is[NL], s_y[NL], s_amp[NL];
    int t = threadIdx.x;
    if (t < 32) sh_h[t] = g_h[t];
    else if (t < 96) sh_m[t - 32] = g_m[t - 32];
    else if (t < 96 + NL) {
        int l = t - 96;
        s_nu0[l] = g_nu0[l]; s_is[l] = g_isig[l]; s_y[l] = g_y[l]; s_amp[l] = g_amp[l];
    }
    __syncthreads();

    const int stride4 = NWL / 4;
    int i = blockIdx.x * blockDim.x + t;

    uint64_t pL = make_policy_last();    // mw3: keep resident
    uint64_t pF = make_policy_first();   // everything else: stream through

    float4 wl = ldg_pol4(&wl4[i], pF);

    // Per-block row-order rotation.
    int rotC = (blockIdx.x * 7)  & 31;
    int rotM = (blockIdx.x * 11) & 63;

    float4 buf[2][4];

    // ---- Continuum dot: 32 rows, 8 chunks of 4, prefetch depth 2 ----
    float4 c = ldg_pol4(&cb2[i], pF);
#pragma unroll
    for (int j = 0; j < 4; j++) {
        int kk = (j + rotC) & 31;
        buf[0][j] = ldg_pol4(&cw2[kk * stride4 + i], pF);
    }
#pragma unroll
    for (int ch = 0; ch < 8; ch++) {
        int cur = ch & 1;
        if (ch < 7) {
#pragma unroll
            for (int j = 0; j < 4; j++) {
                int kk = ((ch + 1) * 4 + j + rotC) & 31;
                buf[cur ^ 1][j] = ldg_pol4(&cw2[kk * stride4 + i], pF);
            }
        }
#pragma unroll
        for (int j = 0; j < 4; j++) {
            int kk = (ch * 4 + j + rotC) & 31;
            float hk = sh_h[kk];
            float4 w = buf[cur][j];
            c.x = fmaf(hk, w.x, c.x);
            c.y = fmaf(hk, w.y, c.y);
            c.z = fmaf(hk, w.z, c.z);
            c.w = fmaf(hk, w.w, c.w);
        }
    }

    // ---- Mixing dot: 64 rows, 16 chunks of 4, prefetch depth 2 ----
    float4 d = ldg_pol4(&mb3[i], pF);
#pragma unroll
    for (int j = 0; j < 4; j++) {
        int kk = (j + rotM) & 63;
        buf[0][j] = ldg_pol4(&mw3[kk * stride4 + i], pL);
    }
#pragma unroll
    for (int ch = 0; ch < 16; ch++) {
        int cur = ch & 1;
        if (ch < 15) {
#pragma unroll
            for (int j = 0; j < 4; j++) {
                int kk = ((ch + 1) * 4 + j + rotM) & 63;
                buf[cur ^ 1][j] = ldg_pol4(&mw3[kk * stride4 + i], pL);
            }
        }
#pragma unroll
        for (int j = 0; j < 4; j++) {
            int kk = (ch * 4 + j + rotM) & 63;
            float mk = sh_m[kk];
            float4 w = buf[cur][j];
            d.x = fmaf(mk, w.x, d.x);
            d.y = fmaf(mk, w.y, d.y);
            d.z = fmaf(mk, w.z, d.z);
            d.w = fmaf(mk, w.w, d.w);
        }
    }

    float cr0 = line_sum(wl.x, s_nu0, s_is, s_y, s_amp) + softplusf_(c.x);
    float cr1 = line_sum(wl.y, s_nu0, s_is, s_y, s_amp) + softplusf_(c.y);
    float cr2 = line_sum(wl.z, s_nu0, s_is, s_y, s_amp) + softplusf_(c.z);
    float cr3 = line_sum(wl.w, s_nu0, s_is, s_y, s_amp) + softplusf_(c.w);

    float4 o;
    o.x = cr0 * (1.0f + 0.1f * (sigmoidf_(d.x) - 0.5f));
    o.y = cr1 * (1.0f + 0.1f * (sigmoidf_(d.y) - 0.5f));
    o.z = cr2 * (1.0f + 0.1f * (sigmoidf_(d.z) - 0.5f));
    o.w = cr3 * (1.0f + 0.1f * (sigmoidf_(d.w) - 0.5f));
    out[i] = o;
}

extern "C" void kernel_launch(void* const* d_in, const int* in_sizes, int n_in,
                              void* d_out, int out_size) {
    const float* wl   = (const float*)d_in[0];
    const float* pT   = (const float*)d_in[1];
    const float* pP   = (const float*)d_in[2];
    const float* po3  = (const float*)d_in[3];
    const float* ph2o = (const float*)d_in[4];
    const float* pco2 = (const float*)d_in[5];
    const float* mw1  = (const float*)d_in[6];
    const float* mb1  = (const float*)d_in[7];
    const float* mw2  = (const float*)d_in[8];
    const float* mb2  = (const float*)d_in[9];
    const float* mw3  = (const float*)d_in[10];
    const float* mb3  = (const float*)d_in[11];
    const float* cw1  = (const float*)d_in[12];
    const float* cb1  = (const float*)d_in[13];
    const float* cw2  = (const float*)d_in[14];
    const float* cb2  = (const float*)d_in[15];

    prep_kernel<<<1, 64>>>(wl, pT, pP, po3, ph2o, pco2,
                           mw1, mb1, mw2, mb2, cw1, cb1, cw2, cb2);

    const int vec = NWL / 4;           // 65536 threads, 4 wl each
    main_kernel<<<vec / 128, 128>>>((const float4*)wl,
                                    (const float4*)cw2, (const float4*)cb2,
                                    (const float4*)mw3, (const float4*)mb3,
                                    (float4*)d_out);
}